// round 8
// baseline (speedup 1.0000x reference)
#include <cuda_runtime.h>
#include <math.h>

#define Bv 4
#define Sv 2048
#define Dv 1024
#define Hv 16
#define DKv 64
#define Nqkv (3*Hv*DKv)   // 3072

// ---------------- scratch (device globals) ----------------
__device__ unsigned g_normed[(size_t)Bv*Sv*Dv];     // tf32 bits
__device__ unsigned g_wqkv[(size_t)Dv*Nqkv];        // tf32 bits
__device__ unsigned g_wo[(size_t)Dv*Dv];            // tf32 bits
__device__ unsigned g_q[(size_t)Bv*Hv*Sv*DKv];      // tf32 bits [b][h][s][dk]
__device__ unsigned g_k[(size_t)Bv*Hv*Sv*DKv];
__device__ unsigned g_v[(size_t)Bv*Hv*Sv*DKv];
__device__ unsigned g_ctx[(size_t)Bv*Sv*Dv];        // tf32 bits [b][s][h*64+dk]
__device__ float    g_bias[Hv*Sv];                  // [h][distance]

// ---------------- helpers ----------------
__device__ __forceinline__ unsigned f2t(float x) {
    unsigned r; asm("cvt.rna.tf32.f32 %0, %1;" : "=r"(r) : "f"(x)); return r;
}
__device__ __forceinline__ void mma8(float c[4], const unsigned a[4], const unsigned b[2]) {
    asm volatile(
        "mma.sync.aligned.m16n8k8.row.col.f32.tf32.tf32.f32 "
        "{%0,%1,%2,%3}, {%4,%5,%6,%7}, {%8,%9}, {%0,%1,%2,%3};"
        : "+f"(c[0]), "+f"(c[1]), "+f"(c[2]), "+f"(c[3])
        : "r"(a[0]), "r"(a[1]), "r"(a[2]), "r"(a[3]), "r"(b[0]), "r"(b[1]));
}
__device__ __forceinline__ void ldsm4(unsigned a[4], const unsigned* p) {
    unsigned addr = (unsigned)__cvta_generic_to_shared(p);
    asm volatile("ldmatrix.sync.aligned.m8n8.x4.shared.b16 {%0,%1,%2,%3}, [%4];"
        : "=r"(a[0]), "=r"(a[1]), "=r"(a[2]), "=r"(a[3]) : "r"(addr));
}
__device__ __forceinline__ void ldsm2(unsigned b[2], const unsigned* p) {
    unsigned addr = (unsigned)__cvta_generic_to_shared(p);
    asm volatile("ldmatrix.sync.aligned.m8n8.x2.shared.b16 {%0,%1}, [%2];"
        : "=r"(b[0]), "=r"(b[1]) : "r"(addr));
}
__device__ __forceinline__ void cp16(unsigned sdst, const void* gsrc) {
    asm volatile("cp.async.cg.shared.global [%0], [%1], 16;" :: "r"(sdst), "l"(gsrc));
}
#define CP_COMMIT() asm volatile("cp.async.commit_group;")
#define CP_WAIT1()  asm volatile("cp.async.wait_group 1;")
#define CP_WAIT0()  asm volatile("cp.async.wait_group 0;")

// ---------------- fused preprocessing: rmsnorm + 2 weight converts + bias table ----------------
__global__ __launch_bounds__(256) void pre_kernel(const float* __restrict__ x,
                                                  const float* __restrict__ w,
                                                  const float* __restrict__ Wqkv,
                                                  const float* __restrict__ Wo,
                                                  const float* __restrict__ rel_bias) {
    int bx = blockIdx.x;
    int t = threadIdx.x;
    if (bx < 8192) {
        const float* xr = x + (size_t)bx * Dv;
        unsigned* nr = g_normed + (size_t)bx * Dv;
        float4 v = ((const float4*)xr)[t];
        float ss = v.x*v.x + v.y*v.y + v.z*v.z + v.w*v.w;
        #pragma unroll
        for (int o = 16; o; o >>= 1) ss += __shfl_xor_sync(0xffffffffu, ss, o);
        __shared__ float sred[8];
        if ((t & 31) == 0) sred[t >> 5] = ss;
        __syncthreads();
        if (t < 8) {
            float s2 = sred[t];
            #pragma unroll
            for (int o = 4; o; o >>= 1) s2 += __shfl_xor_sync(0xffu, s2, o);
            if (t == 0) sred[0] = s2;
        }
        __syncthreads();
        float inv = rsqrtf(sred[0] * (1.0f / Dv) + 1e-6f);
        float4 wv = ((const float4*)w)[t];
        uint4 o4;
        o4.x = f2t(v.x * inv * wv.x);
        o4.y = f2t(v.y * inv * wv.y);
        o4.z = f2t(v.z * inv * wv.z);
        o4.w = f2t(v.w * inv * wv.w);
        ((uint4*)nr)[t] = o4;
    } else if (bx < 8192 + 3072) {
        int i = (bx - 8192) * 256 + t;
        float4 v = ((const float4*)Wqkv)[i];
        uint4 o; o.x = f2t(v.x); o.y = f2t(v.y); o.z = f2t(v.z); o.w = f2t(v.w);
        ((uint4*)g_wqkv)[i] = o;
    } else if (bx < 8192 + 3072 + 1024) {
        int i = (bx - 8192 - 3072) * 256 + t;
        float4 v = ((const float4*)Wo)[i];
        uint4 o; o.x = f2t(v.x); o.y = f2t(v.y); o.z = f2t(v.z); o.w = f2t(v.w);
        ((uint4*)g_wo)[i] = o;
    } else {
        int d = (bx - 12288) * 256 + t;
        int bucket;
        if (d < 16) bucket = d;
        else {
            float v = (logf((float)d / 16.0f) / 2.0794415416798357f) * 16.0f;
            bucket = 16 + (int)v;
            if (bucket > 31) bucket = 31;
        }
        #pragma unroll
        for (int h = 0; h < Hv; ++h)
            g_bias[h * Sv + d] = rel_bias[bucket * Hv + h];
    }
}

// ---------------- tf32 HMMA GEMM: [8192,1024] x [1024,N] ----------------
// block 128x256, 16 warps (4x4), warp tile 32x64, K-tile 32, cp.async double buffer
// MODE 0: scatter qkv (tf32 out). MODE 1: out = acc + hidden (fp32 out).
template<int N, int MODE>
__global__ __launch_bounds__(512, 1) void mm_kernel(const unsigned* __restrict__ A,
                                                    const unsigned* __restrict__ Bm,
                                                    const float* __restrict__ hidden,
                                                    float* __restrict__ outp) {
    const int LDA = 36, LDB = 264;
    const int ASZ = 128 * LDA;          // 4608 u32 per buffer
    const int BSZ = 32 * LDB;           // 8448 u32 per buffer
    extern __shared__ unsigned sh[];
    unsigned* As = sh;
    unsigned* Bs = sh + 2 * ASZ;

    int m0 = blockIdx.y * 128, n0 = blockIdx.x * 256;
    int tid = threadIdx.x;
    int wid = tid >> 5, l = tid & 31;
    int wm = wid >> 2, wn = wid & 3;     // 4 x 4 warps
    int l4 = l >> 2, lm = l & 3;

    unsigned sAbase = (unsigned)__cvta_generic_to_shared(As);
    unsigned sBbase = (unsigned)__cvta_generic_to_shared(Bs);

    auto issue = [&](int kt, int buf) {
        #pragma unroll
        for (int i = 0; i < 2; ++i) {
            int idx = tid + i * 512;            // A: 128 rows x 8 uint4
            int row = idx >> 3, q = idx & 7;
            cp16(sAbase + (buf * ASZ + row * LDA + q * 4) * 4,
                 A + (size_t)(m0 + row) * Dv + kt * 32 + q * 4);
        }
        #pragma unroll
        for (int i = 0; i < 4; ++i) {
            int idx = tid + i * 512;            // B: 32 k x 64 uint4
            int k = idx >> 6, g = idx & 63;
            cp16(sBbase + (buf * BSZ + k * LDB + g * 4) * 4,
                 Bm + (size_t)(kt * 32 + k) * N + n0 + g * 4);
        }
    };

    float acc[2][8][4];
    #pragma unroll
    for (int t = 0; t < 2; t++)
        #pragma unroll
        for (int u = 0; u < 8; u++)
            #pragma unroll
            for (int e = 0; e < 4; e++) acc[t][u][e] = 0.0f;

    issue(0, 0); CP_COMMIT();
    issue(1, 1); CP_COMMIT();

    const int NT = Dv / 32;   // 32 K-tiles
    int lrow = l & 15;
    int lcol = (l >> 4) << 2;
    for (int kt = 0; kt < NT; ++kt) {
        if (kt + 1 < NT) CP_WAIT1(); else CP_WAIT0();
        __syncthreads();
        const unsigned* Ab = As + (kt & 1) * ASZ;
        const unsigned* Bb = Bs + (kt & 1) * BSZ;
        #pragma unroll
        for (int s = 0; s < 4; ++s) {
            unsigned a[2][4];
            #pragma unroll
            for (int t = 0; t < 2; ++t)
                ldsm4(a[t], Ab + (wm * 32 + t * 16 + lrow) * LDA + s * 8 + lcol);
            unsigned b[8][2];
            #pragma unroll
            for (int u = 0; u < 8; ++u) {
                int cn = wn * 64 + u * 8 + l4;
                b[u][0] = Bb[(s * 8 + lm) * LDB + cn];
                b[u][1] = Bb[(s * 8 + lm + 4) * LDB + cn];
            }
            #pragma unroll
            for (int t = 0; t < 2; ++t)
                #pragma unroll
                for (int u = 0; u < 8; ++u)
                    mma8(acc[t][u], a[t], b[u]);
        }
        __syncthreads();
        if (kt + 2 < NT) issue(kt + 2, kt & 1);
        CP_COMMIT();
    }

    // epilogue
    if (MODE == 0) {
        #pragma unroll
        for (int t = 0; t < 2; ++t) {
            int r = m0 + wm * 32 + t * 16 + l4;
            int b0r = r >> 11, s0r = r & 2047;
            #pragma unroll
            for (int u = 0; u < 8; ++u) {
                int cb = n0 + wn * 64 + u * 8 + lm * 2;
                int three = cb >> 10;
                int rem = cb & 1023;
                int h = rem >> 6, dk = rem & 63;
                unsigned* dst = (three == 0) ? g_q : ((three == 1) ? g_k : g_v);
                size_t off0 = ((((size_t)b0r * Hv + h) * Sv + s0r) * DKv + dk);
                *(uint2*)(dst + off0) = make_uint2(f2t(acc[t][u][0]), f2t(acc[t][u][1]));
                size_t off1 = ((((size_t)b0r * Hv + h) * Sv + (s0r + 8)) * DKv + dk);
                *(uint2*)(dst + off1) = make_uint2(f2t(acc[t][u][2]), f2t(acc[t][u][3]));
            }
        }
    } else {
        #pragma unroll
        for (int t = 0; t < 2; ++t) {
            int r = m0 + wm * 32 + t * 16 + l4;
            #pragma unroll
            for (int u = 0; u < 8; ++u) {
                int cb = n0 + wn * 64 + u * 8 + lm * 2;
                float2 h0 = *(const float2*)(hidden + (size_t)r * Dv + cb);
                *(float2*)(outp + (size_t)r * Dv + cb) =
                    make_float2(acc[t][u][0] + h0.x, acc[t][u][1] + h0.y);
                float2 h1 = *(const float2*)(hidden + (size_t)(r + 8) * Dv + cb);
                *(float2*)(outp + (size_t)(r + 8) * Dv + cb) =
                    make_float2(acc[t][u][2] + h1.x, acc[t][u][3] + h1.y);
            }
        }
    }
}

// ---------------- Flash attention on tf32 HMMA ----------------
// q-tile 128 (8 warps x 16 rows), k-tile 64, single-buffered K/V, 2 CTAs/SM.
__global__ __launch_bounds__(256, 2) void attn_kernel() {
    int qt = (int)(gridDim.x - 1) - (int)blockIdx.x;  // longest blocks first
    int bh = blockIdx.y;
    int b_ = bh >> 4, h = bh & 15;
    int q0 = qt * 128;

    // smem (u32): Q[128][68], K[64][68], V[64][72], P[128][68], bias[192]
    extern __shared__ unsigned sm[];
    unsigned* Qs = sm;                      // 8704
    unsigned* Ks = sm + 8704;               // 4352
    unsigned* Vs = sm + 8704 + 4352;        // 4608
    unsigned* Ps = sm + 8704 + 4352 + 4608; // 8704
    float* bs = (float*)(Ps + 8704);        // 192

    const unsigned* Qg = g_q + (size_t)bh * Sv * DKv;
    const unsigned* Kg = g_k + (size_t)bh * Sv * DKv;
    const unsigned* Vg = g_v + (size_t)bh * Sv * DKv;

    int tid = threadIdx.x, wid = tid >> 5, l = tid & 31;
    int l4 = l >> 2, lm = l & 3;
    int r0 = wid * 16 + l4;
    int lrow = l & 15;
    int lcol = (l >> 4) << 2;

    unsigned sKbase = (unsigned)__cvta_generic_to_shared(Ks);
    unsigned sVbase = (unsigned)__cvta_generic_to_shared(Vs);

    auto issueKV = [&](int kt) {
        int k0 = kt * 64;
        #pragma unroll
        for (int i = 0; i < 4; ++i) {
            int idx = tid + i * 256;
            int row = idx >> 4, q = idx & 15;
            cp16(sKbase + (row * 68 + q * 4) * 4, Kg + (size_t)(k0 + row) * DKv + q * 4);
            cp16(sVbase + (row * 72 + q * 4) * 4, Vg + (size_t)(k0 + row) * DKv + q * 4);
        }
    };

    // stage Q (128x64 u32)
    #pragma unroll
    for (int i = 0; i < 8; ++i) {
        int idx = tid + i * 256;
        int row = idx >> 4, q = idx & 15;
        *(uint4*)&Qs[row * 68 + q * 4] = *(const uint4*)(Qg + (size_t)(q0 + row) * DKv + q * 4);
    }

    int ktmax = 2 * qt + 1;
    issueKV(0); CP_COMMIT();

    float breg = 0.0f;
    if (tid < 192) {
        int dv = q0 + tid - 63;
        breg = (dv >= 0 && dv < Sv) ? g_bias[h * Sv + dv] : 0.0f;
    }

    float m0v = -1e30f, m1v = -1e30f, l0v = 0.0f, l1v = 0.0f;
    float O[8][4];
    #pragma unroll
    for (int u = 0; u < 8; ++u)
        #pragma unroll
        for (int e = 0; e < 4; ++e) O[u][e] = 0.0f;

    for (int kt = 0; kt <= ktmax; ++kt) {
        int k0 = kt * 64;
        if (tid < 192) bs[tid] = breg;
        CP_WAIT0();
        __syncthreads();

        bool active = (k0 <= q0 + wid * 16 + 15);   // warp-uniform
        if (active) {
            // S = Q K^T
            float S[8][4];
            #pragma unroll
            for (int u = 0; u < 8; ++u)
                #pragma unroll
                for (int e = 0; e < 4; ++e) S[u][e] = 0.0f;
            #pragma unroll
            for (int s = 0; s < 8; ++s) {
                unsigned a[4];
                ldsm4(a, Qs + (wid * 16 + lrow) * 68 + s * 8 + lcol);
                #pragma unroll
                for (int u = 0; u < 8; ++u) {
                    unsigned bfr[2];
                    ldsm2(bfr, Ks + (u * 8 + (l & 7)) * 68 + s * 8 + (((l >> 3) & 1) << 2));
                    mma8(S[u], a, bfr);
                }
            }

            // bias + causal, row maxima
            int dq = q0 - k0;
            float mx0 = -1e30f, mx1 = -1e30f;
            #pragma unroll
            for (int u = 0; u < 8; ++u) {
                int c = u * 8 + lm * 2;
                #pragma unroll
                for (int e = 0; e < 2; ++e) {
                    int cc = c + e;
                    int d0 = dq + r0 - cc;
                    S[u][e]     = (d0 >= 0) ? S[u][e] + bs[r0 - cc + 63] : -1e30f;
                    int d1 = dq + r0 + 8 - cc;
                    S[u][2 + e] = (d1 >= 0) ? S[u][2 + e] + bs[r0 + 8 - cc + 63] : -1e30f;
                    mx0 = fmaxf(mx0, S[u][e]);
                    mx1 = fmaxf(mx1, S[u][2 + e]);
                }
            }
            mx0 = fmaxf(mx0, __shfl_xor_sync(0xffffffffu, mx0, 1));
            mx0 = fmaxf(mx0, __shfl_xor_sync(0xffffffffu, mx0, 2));
            mx1 = fmaxf(mx1, __shfl_xor_sync(0xffffffffu, mx1, 1));
            mx1 = fmaxf(mx1, __shfl_xor_sync(0xffffffffu, mx1, 2));

            float mn0 = fmaxf(m0v, mx0), mn1 = fmaxf(m1v, mx1);
            float sc0 = __expf(m0v - mn0), sc1 = __expf(m1v - mn1);
            m0v = mn0; m1v = mn1;
            float rs0 = 0.0f, rs1 = 0.0f;
            #pragma unroll
            for (int u = 0; u < 8; ++u) {
                #pragma unroll
                for (int e = 0; e < 2; ++e) {
                    float p0 = __expf(S[u][e] - mn0);     S[u][e] = p0;     rs0 += p0;
                    float p1 = __expf(S[u][2 + e] - mn1); S[u][2 + e] = p1; rs1 += p1;
                }
            }
            rs0 += __shfl_xor_sync(0xffffffffu, rs0, 1);
            rs0 += __shfl_xor_sync(0xffffffffu, rs0, 2);
            rs1 += __shfl_xor_sync(0xffffffffu, rs1, 1);
            rs1 += __shfl_xor_sync(0xffffffffu, rs1, 2);
            l0v = l0v * sc0 + rs0;
            l1v = l1v * sc1 + rs1;
            #pragma unroll
            for (int u = 0; u < 8; ++u) {
                O[u][0] *= sc0; O[u][1] *= sc0;
                O[u][2] *= sc1; O[u][3] *= sc1;
            }
            // P -> tf32 smem
            #pragma unroll
            for (int u = 0; u < 8; ++u) {
                int c = u * 8 + lm * 2;
                Ps[r0 * 68 + c]           = f2t(S[u][0]);
                Ps[r0 * 68 + c + 1]       = f2t(S[u][1]);
                Ps[(r0 + 8) * 68 + c]     = f2t(S[u][2]);
                Ps[(r0 + 8) * 68 + c + 1] = f2t(S[u][3]);
            }
            __syncwarp();

            // O += P V
            #pragma unroll
            for (int s = 0; s < 8; ++s) {
                unsigned a[4];
                ldsm4(a, Ps + (wid * 16 + lrow) * 68 + s * 8 + lcol);
                #pragma unroll
                for (int u = 0; u < 8; ++u) {
                    unsigned bfr[2];
                    int n = u * 8 + l4;
                    bfr[0] = Vs[(s * 8 + lm) * 72 + n];
                    bfr[1] = Vs[(s * 8 + lm + 4) * 72 + n];
                    mma8(O[u], a, bfr);
                }
            }
        }
        // prefetch next bias into registers
        if (kt + 1 <= ktmax && tid < 192) {
            int dv = q0 - (kt + 1) * 64 + tid - 63;
            breg = (dv >= 0 && dv < Sv) ? g_bias[h * Sv + dv] : 0.0f;
        }
        __syncthreads();
        if (kt + 1 <= ktmax) { issueKV(kt + 1); CP_COMMIT(); }
    }

    // epilogue: ctx (tf32) in [b][s][h*64+dk]
    float inv0 = 1.0f / l0v, inv1 = 1.0f / l1v;
    int gr = q0 + r0;
    #pragma unroll
    for (int u = 0; u < 8; ++u) {
        int dk = h * 64 + u * 8 + lm * 2;
        size_t o0 = ((size_t)(b_ * Sv + gr)) * Dv + dk;
        *(uint2*)(g_ctx + o0) = make_uint2(f2t(O[u][0] * inv0), f2t(O[u][1] * inv0));
        size_t o1 = ((size_t)(b_ * Sv + gr + 8)) * Dv + dk;
        *(uint2*)(g_ctx + o1) = make_uint2(f2t(O[u][2] * inv1), f2t(O[u][3] * inv1));
    }
}

// ---------------- launch ----------------
extern "C" void kernel_launch(void* const* d_in, const int* in_sizes, int n_in,
                              void* d_out, int out_size) {
    (void)in_sizes; (void)n_in; (void)out_size;
    const float* hidden   = (const float*)d_in[0];
    const float* rms_w    = (const float*)d_in[2];
    const float* W_qkv    = (const float*)d_in[3];
    const float* W_o      = (const float*)d_in[4];
    const float* rel_bias = (const float*)d_in[5];
    float* out = (float*)d_out;

    unsigned* wqkv_p; cudaGetSymbolAddress((void**)&wqkv_p, g_wqkv);
    unsigned* wo_p;   cudaGetSymbolAddress((void**)&wo_p, g_wo);
    unsigned* nrm_p;  cudaGetSymbolAddress((void**)&nrm_p, g_normed);
    unsigned* ctx_p;  cudaGetSymbolAddress((void**)&ctx_p, g_ctx);

    const int MM_SMEM = (2 * (128 * 36 + 32 * 264)) * 4;                 // 104448
    const int AT_SMEM = (8704 + 4352 + 4608 + 8704) * 4 + 192 * 4 + 64;  // ~106 KB
    cudaFuncSetAttribute(mm_kernel<Nqkv, 0>, cudaFuncAttributeMaxDynamicSharedMemorySize, MM_SMEM);
    cudaFuncSetAttribute(mm_kernel<Dv, 1>,   cudaFuncAttributeMaxDynamicSharedMemorySize, MM_SMEM);
    cudaFuncSetAttribute(attn_kernel,        cudaFuncAttributeMaxDynamicSharedMemorySize, AT_SMEM);

    pre_kernel<<<8192 + 3072 + 1024 + 8, 256>>>(hidden, rms_w, W_qkv, W_o, rel_bias);
    mm_kernel<Nqkv, 0><<<dim3(Nqkv / 256, (Bv * Sv) / 128), 512, MM_SMEM>>>(nrm_p, wqkv_p, nullptr, nullptr);
    attn_kernel<<<dim3(Sv / 128, Bv * Hv), 256, AT_SMEM>>>();
    mm_kernel<Dv, 1><<<dim3(Dv / 256, (Bv * Sv) / 128), 512, MM_SMEM>>>(ctx_p, wo_p, hidden, out);
}

// round 11
// speedup vs baseline: 1.5918x; 1.5918x over previous
#include <cuda_runtime.h>
#include <math.h>

#define Bv 4
#define Sv 2048
#define Dv 1024
#define Hv 16
#define DKv 64
#define Nqkv (3*Hv*DKv)   // 3072

// ---------------- scratch (device globals) ----------------
__device__ unsigned g_normed[(size_t)Bv*Sv*Dv];     // tf32 bits
__device__ unsigned g_wqkv[(size_t)Dv*Nqkv];        // tf32 bits
__device__ unsigned g_wo[(size_t)Dv*Dv];            // tf32 bits
__device__ unsigned g_q[(size_t)Bv*Hv*Sv*DKv];      // tf32 bits [b][h][s][dk]
__device__ unsigned g_k[(size_t)Bv*Hv*Sv*DKv];
__device__ unsigned g_v[(size_t)Bv*Hv*Sv*DKv];
__device__ unsigned g_ctx[(size_t)Bv*Sv*Dv];        // tf32 bits [b][s][h*64+dk]
__device__ float    g_bias[Hv*Sv];                  // [h][distance]

// ---------------- helpers ----------------
__device__ __forceinline__ unsigned f2t(float x) {
    unsigned r; asm("cvt.rna.tf32.f32 %0, %1;" : "=r"(r) : "f"(x)); return r;
}
__device__ __forceinline__ void mma8(float c[4], const unsigned a[4], const unsigned b[2]) {
    asm volatile(
        "mma.sync.aligned.m16n8k8.row.col.f32.tf32.tf32.f32 "
        "{%0,%1,%2,%3}, {%4,%5,%6,%7}, {%8,%9}, {%0,%1,%2,%3};"
        : "+f"(c[0]), "+f"(c[1]), "+f"(c[2]), "+f"(c[3])
        : "r"(a[0]), "r"(a[1]), "r"(a[2]), "r"(a[3]), "r"(b[0]), "r"(b[1]));
}
__device__ __forceinline__ void ldsm4(unsigned a[4], const unsigned* p) {
    unsigned addr = (unsigned)__cvta_generic_to_shared(p);
    asm volatile("ldmatrix.sync.aligned.m8n8.x4.shared.b16 {%0,%1,%2,%3}, [%4];"
        : "=r"(a[0]), "=r"(a[1]), "=r"(a[2]), "=r"(a[3]) : "r"(addr));
}
__device__ __forceinline__ void ldsm2(unsigned b[2], const unsigned* p) {
    unsigned addr = (unsigned)__cvta_generic_to_shared(p);
    asm volatile("ldmatrix.sync.aligned.m8n8.x2.shared.b16 {%0,%1}, [%2];"
        : "=r"(b[0]), "=r"(b[1]) : "r"(addr));
}
__device__ __forceinline__ void cp16(unsigned sdst, const void* gsrc) {
    asm volatile("cp.async.cg.shared.global [%0], [%1], 16;" :: "r"(sdst), "l"(gsrc));
}
#define CP_COMMIT() asm volatile("cp.async.commit_group;")
#define CP_WAIT1()  asm volatile("cp.async.wait_group 1;")
#define CP_WAIT0()  asm volatile("cp.async.wait_group 0;")

// ---------------- fused preprocessing: rmsnorm + 2 weight converts + bias table ----------------
__global__ __launch_bounds__(256) void pre_kernel(const float* __restrict__ x,
                                                  const float* __restrict__ w,
                                                  const float* __restrict__ Wqkv,
                                                  const float* __restrict__ Wo,
                                                  const float* __restrict__ rel_bias) {
    int bx = blockIdx.x;
    int t = threadIdx.x;
    if (bx < 8192) {
        const float* xr = x + (size_t)bx * Dv;
        unsigned* nr = g_normed + (size_t)bx * Dv;
        float4 v = ((const float4*)xr)[t];
        float ss = v.x*v.x + v.y*v.y + v.z*v.z + v.w*v.w;
        #pragma unroll
        for (int o = 16; o; o >>= 1) ss += __shfl_xor_sync(0xffffffffu, ss, o);
        __shared__ float sred[8];
        if ((t & 31) == 0) sred[t >> 5] = ss;
        __syncthreads();
        if (t < 8) {
            float s2 = sred[t];
            #pragma unroll
            for (int o = 4; o; o >>= 1) s2 += __shfl_xor_sync(0xffu, s2, o);
            if (t == 0) sred[0] = s2;
        }
        __syncthreads();
        float inv = rsqrtf(sred[0] * (1.0f / Dv) + 1e-6f);
        float4 wv = ((const float4*)w)[t];
        uint4 o4;
        o4.x = f2t(v.x * inv * wv.x);
        o4.y = f2t(v.y * inv * wv.y);
        o4.z = f2t(v.z * inv * wv.z);
        o4.w = f2t(v.w * inv * wv.w);
        ((uint4*)nr)[t] = o4;
    } else if (bx < 8192 + 3072) {
        int i = (bx - 8192) * 256 + t;
        float4 v = ((const float4*)Wqkv)[i];
        uint4 o; o.x = f2t(v.x); o.y = f2t(v.y); o.z = f2t(v.z); o.w = f2t(v.w);
        ((uint4*)g_wqkv)[i] = o;
    } else if (bx < 8192 + 3072 + 1024) {
        int i = (bx - 8192 - 3072) * 256 + t;
        float4 v = ((const float4*)Wo)[i];
        uint4 o; o.x = f2t(v.x); o.y = f2t(v.y); o.z = f2t(v.z); o.w = f2t(v.w);
        ((uint4*)g_wo)[i] = o;
    } else {
        int d = (bx - 12288) * 256 + t;
        int bucket;
        if (d < 16) bucket = d;
        else {
            float v = (logf((float)d / 16.0f) / 2.0794415416798357f) * 16.0f;
            bucket = 16 + (int)v;
            if (bucket > 31) bucket = 31;
        }
        #pragma unroll
        for (int h = 0; h < Hv; ++h)
            g_bias[h * Sv + d] = rel_bias[bucket * Hv + h];
    }
}

// ---------------- tf32 HMMA GEMM: [8192,1024] x [1024,N] ----------------
// block 128x256, 8 warps (2x4), warp tile 64x64, K-tile 32, cp.async double buffer,
// register-fragment double-buffering across s-steps (hides LDS latency).
// MODE 0: scatter qkv (tf32 out). MODE 1: out = acc + hidden (fp32 out).
template<int N, int MODE>
__global__ __launch_bounds__(256, 1) void mm_kernel(const unsigned* __restrict__ A,
                                                    const unsigned* __restrict__ Bm,
                                                    const float* __restrict__ hidden,
                                                    float* __restrict__ outp) {
    const int LDA = 36, LDB = 264;
    const int ASZ = 128 * LDA;          // 4608 u32 per buffer
    const int BSZ = 32 * LDB;           // 8448 u32 per buffer
    extern __shared__ unsigned sh[];
    unsigned* As = sh;
    unsigned* Bs = sh + 2 * ASZ;

    int m0 = blockIdx.y * 128, n0 = blockIdx.x * 256;
    int tid = threadIdx.x;
    int wid = tid >> 5, l = tid & 31;
    int wm = wid >> 2, wn = wid & 3;     // 2 x 4 warps
    int l4 = l >> 2, lm = l & 3;

    unsigned sAbase = (unsigned)__cvta_generic_to_shared(As);
    unsigned sBbase = (unsigned)__cvta_generic_to_shared(Bs);

    auto issue = [&](int kt, int buf) {
        #pragma unroll
        for (int i = 0; i < 4; ++i) {
            int idx = tid + i * 256;            // A: 128 rows x 8 uint4
            int row = idx >> 3, q = idx & 7;
            cp16(sAbase + (buf * ASZ + row * LDA + q * 4) * 4,
                 A + (size_t)(m0 + row) * Dv + kt * 32 + q * 4);
        }
        #pragma unroll
        for (int i = 0; i < 8; ++i) {
            int idx = tid + i * 256;            // B: 32 k x 64 uint4
            int k = idx >> 6, g = idx & 63;
            cp16(sBbase + (buf * BSZ + k * LDB + g * 4) * 4,
                 Bm + (size_t)(kt * 32 + k) * N + n0 + g * 4);
        }
    };

    float acc[4][8][4];
    #pragma unroll
    for (int t = 0; t < 4; t++)
        #pragma unroll
        for (int u = 0; u < 8; u++)
            #pragma unroll
            for (int e = 0; e < 4; e++) acc[t][u][e] = 0.0f;

    issue(0, 0); CP_COMMIT();
    issue(1, 1); CP_COMMIT();

    const int NT = Dv / 32;   // 32 K-tiles
    int lrow = l & 15;
    int lcol = (l >> 4) << 2;

    unsigned afr[2][4][4], bfr[2][8][2];

    for (int kt = 0; kt < NT; ++kt) {
        if (kt + 1 < NT) CP_WAIT1(); else CP_WAIT0();
        __syncthreads();
        const unsigned* Ab = As + (kt & 1) * ASZ;
        const unsigned* Bb = Bs + (kt & 1) * BSZ;

        // preload s=0 fragments
        #pragma unroll
        for (int t = 0; t < 4; ++t)
            ldsm4(afr[0][t], Ab + (wm * 64 + t * 16 + lrow) * LDA + lcol);
        #pragma unroll
        for (int u = 0; u < 8; ++u) {
            int cn = wn * 64 + u * 8 + l4;
            bfr[0][u][0] = Bb[lm * LDB + cn];
            bfr[0][u][1] = Bb[(lm + 4) * LDB + cn];
        }

        #pragma unroll
        for (int s = 0; s < 4; ++s) {
            int cur = s & 1, nxt = cur ^ 1;
            if (s < 3) {
                // prefetch s+1 fragments while s's MMAs issue
                #pragma unroll
                for (int t = 0; t < 4; ++t)
                    ldsm4(afr[nxt][t], Ab + (wm * 64 + t * 16 + lrow) * LDA + (s + 1) * 8 + lcol);
                #pragma unroll
                for (int u = 0; u < 8; ++u) {
                    int cn = wn * 64 + u * 8 + l4;
                    bfr[nxt][u][0] = Bb[((s + 1) * 8 + lm) * LDB + cn];
                    bfr[nxt][u][1] = Bb[((s + 1) * 8 + lm + 4) * LDB + cn];
                }
            }
            #pragma unroll
            for (int t = 0; t < 4; ++t)
                #pragma unroll
                for (int u = 0; u < 8; ++u)
                    mma8(acc[t][u], afr[cur][t], bfr[cur][u]);
        }
        __syncthreads();
        if (kt + 2 < NT) issue(kt + 2, kt & 1);
        CP_COMMIT();
    }

    // epilogue
    if (MODE == 0) {
        #pragma unroll
        for (int t = 0; t < 4; ++t) {
            int r = m0 + wm * 64 + t * 16 + l4;
            int b0r = r >> 11, s0r = r & 2047;
            #pragma unroll
            for (int u = 0; u < 8; ++u) {
                int cb = n0 + wn * 64 + u * 8 + lm * 2;
                int three = cb >> 10;
                int rem = cb & 1023;
                int h = rem >> 6, dk = rem & 63;
                unsigned* dst = (three == 0) ? g_q : ((three == 1) ? g_k : g_v);
                size_t off0 = ((((size_t)b0r * Hv + h) * Sv + s0r) * DKv + dk);
                *(uint2*)(dst + off0) = make_uint2(f2t(acc[t][u][0]), f2t(acc[t][u][1]));
                size_t off1 = ((((size_t)b0r * Hv + h) * Sv + (s0r + 8)) * DKv + dk);
                *(uint2*)(dst + off1) = make_uint2(f2t(acc[t][u][2]), f2t(acc[t][u][3]));
            }
        }
    } else {
        #pragma unroll
        for (int t = 0; t < 4; ++t) {
            int r = m0 + wm * 64 + t * 16 + l4;
            #pragma unroll
            for (int u = 0; u < 8; ++u) {
                int cb = n0 + wn * 64 + u * 8 + lm * 2;
                float2 h0 = *(const float2*)(hidden + (size_t)r * Dv + cb);
                *(float2*)(outp + (size_t)r * Dv + cb) =
                    make_float2(acc[t][u][0] + h0.x, acc[t][u][1] + h0.y);
                float2 h1 = *(const float2*)(hidden + (size_t)(r + 8) * Dv + cb);
                *(float2*)(outp + (size_t)(r + 8) * Dv + cb) =
                    make_float2(acc[t][u][2] + h1.x, acc[t][u][3] + h1.y);
            }
        }
    }
}

// ---------------- Flash attention on tf32 HMMA (round-7 proven version) ----------------
// q-tile 128 (8 warps x 16 rows), k-tile 64, cp.async double-buffered K/V.
__global__ __launch_bounds__(256) void attn_kernel() {
    int qt = (int)(gridDim.x - 1) - (int)blockIdx.x;  // longest blocks first
    int bh = blockIdx.y;
    int b_ = bh >> 4, h = bh & 15;
    int q0 = qt * 128;

    // smem (u32 offsets): Q[128][68], K 2x[64][68], V 2x[64][72], P[128][68], bias[192]
    extern __shared__ unsigned sm[];
    unsigned* Qs = sm;                       // 8704
    unsigned* Ks = sm + 8704;                // 2 x 4352
    unsigned* Vs = sm + 8704 + 8704;         // 2 x 4608
    unsigned* Ps = sm + 8704 + 8704 + 9216;  // 8704
    float* bs = (float*)(Ps + 8704);         // 192

    const unsigned* Qg = g_q + (size_t)bh * Sv * DKv;
    const unsigned* Kg = g_k + (size_t)bh * Sv * DKv;
    const unsigned* Vg = g_v + (size_t)bh * Sv * DKv;

    int tid = threadIdx.x, wid = tid >> 5, l = tid & 31;
    int l4 = l >> 2, lm = l & 3;
    int r0 = wid * 16 + l4;
    int lrow = l & 15;
    int lcol = (l >> 4) << 2;

    unsigned sKbase = (unsigned)__cvta_generic_to_shared(Ks);
    unsigned sVbase = (unsigned)__cvta_generic_to_shared(Vs);

    auto issueKV = [&](int kt, int buf) {
        int k0 = kt * 64;
        #pragma unroll
        for (int i = 0; i < 4; ++i) {
            int idx = tid + i * 256;
            int row = idx >> 4, q = idx & 15;
            cp16(sKbase + (buf * 4352 + row * 68 + q * 4) * 4,
                 Kg + (size_t)(k0 + row) * DKv + q * 4);
            cp16(sVbase + (buf * 4608 + row * 72 + q * 4) * 4,
                 Vg + (size_t)(k0 + row) * DKv + q * 4);
        }
    };

    // stage Q (128x64 u32)
    #pragma unroll
    for (int i = 0; i < 8; ++i) {
        int idx = tid + i * 256;
        int row = idx >> 4, q = idx & 15;
        *(uint4*)&Qs[row * 68 + q * 4] = *(const uint4*)(Qg + (size_t)(q0 + row) * DKv + q * 4);
    }

    int ktmax = 2 * qt + 1;
    issueKV(0, 0); CP_COMMIT();

    float breg = 0.0f;
    if (tid < 192) {
        int dv = q0 + tid - 63;
        breg = (dv >= 0 && dv < Sv) ? g_bias[h * Sv + dv] : 0.0f;
    }

    float m0v = -1e30f, m1v = -1e30f, l0v = 0.0f, l1v = 0.0f;
    float O[8][4];
    #pragma unroll
    for (int u = 0; u < 8; ++u)
        #pragma unroll
        for (int e = 0; e < 4; ++e) O[u][e] = 0.0f;

    for (int kt = 0; kt <= ktmax; ++kt) {
        int k0 = kt * 64;
        int buf = kt & 1;
        if (kt + 1 <= ktmax) issueKV(kt + 1, buf ^ 1);
        CP_COMMIT();
        if (tid < 192) bs[tid] = breg;
        if (kt == ktmax) CP_WAIT0(); else CP_WAIT1();
        __syncthreads();

        const unsigned* Kb = Ks + buf * 4352;
        const unsigned* Vb = Vs + buf * 4608;

        bool active = (k0 <= q0 + wid * 16 + 15);   // warp-uniform
        if (active) {
            // S = Q K^T
            float S[8][4];
            #pragma unroll
            for (int u = 0; u < 8; ++u)
                #pragma unroll
                for (int e = 0; e < 4; ++e) S[u][e] = 0.0f;
            #pragma unroll
            for (int s = 0; s < 8; ++s) {
                unsigned a[4];
                ldsm4(a, Qs + (wid * 16 + lrow) * 68 + s * 8 + lcol);
                #pragma unroll
                for (int u = 0; u < 8; ++u) {
                    unsigned bfr[2];
                    ldsm2(bfr, Kb + (u * 8 + (l & 7)) * 68 + s * 8 + (((l >> 3) & 1) << 2));
                    mma8(S[u], a, bfr);
                }
            }

            // bias + causal, row maxima
            int dq = q0 - k0;
            float mx0 = -1e30f, mx1 = -1e30f;
            #pragma unroll
            for (int u = 0; u < 8; ++u) {
                int c = u * 8 + lm * 2;
                #pragma unroll
                for (int e = 0; e < 2; ++e) {
                    int cc = c + e;
                    int d0 = dq + r0 - cc;
                    S[u][e]     = (d0 >= 0) ? S[u][e] + bs[r0 - cc + 63] : -1e30f;
                    int d1 = dq + r0 + 8 - cc;
                    S[u][2 + e] = (d1 >= 0) ? S[u][2 + e] + bs[r0 + 8 - cc + 63] : -1e30f;
                    mx0 = fmaxf(mx0, S[u][e]);
                    mx1 = fmaxf(mx1, S[u][2 + e]);
                }
            }
            mx0 = fmaxf(mx0, __shfl_xor_sync(0xffffffffu, mx0, 1));
            mx0 = fmaxf(mx0, __shfl_xor_sync(0xffffffffu, mx0, 2));
            mx1 = fmaxf(mx1, __shfl_xor_sync(0xffffffffu, mx1, 1));
            mx1 = fmaxf(mx1, __shfl_xor_sync(0xffffffffu, mx1, 2));

            float mn0 = fmaxf(m0v, mx0), mn1 = fmaxf(m1v, mx1);
            float sc0 = __expf(m0v - mn0), sc1 = __expf(m1v - mn1);
            m0v = mn0; m1v = mn1;
            float rs0 = 0.0f, rs1 = 0.0f;
            #pragma unroll
            for (int u = 0; u < 8; ++u) {
                #pragma unroll
                for (int e = 0; e < 2; ++e) {
                    float p0 = __expf(S[u][e] - mn0);     S[u][e] = p0;     rs0 += p0;
                    float p1 = __expf(S[u][2 + e] - mn1); S[u][2 + e] = p1; rs1 += p1;
                }
            }
            rs0 += __shfl_xor_sync(0xffffffffu, rs0, 1);
            rs0 += __shfl_xor_sync(0xffffffffu, rs0, 2);
            rs1 += __shfl_xor_sync(0xffffffffu, rs1, 1);
            rs1 += __shfl_xor_sync(0xffffffffu, rs1, 2);
            l0v = l0v * sc0 + rs0;
            l1v = l1v * sc1 + rs1;
            #pragma unroll
            for (int u = 0; u < 8; ++u) {
                O[u][0] *= sc0; O[u][1] *= sc0;
                O[u][2] *= sc1; O[u][3] *= sc1;
            }
            // P -> tf32 smem
            #pragma unroll
            for (int u = 0; u < 8; ++u) {
                int c = u * 8 + lm * 2;
                Ps[r0 * 68 + c]           = f2t(S[u][0]);
                Ps[r0 * 68 + c + 1]       = f2t(S[u][1]);
                Ps[(r0 + 8) * 68 + c]     = f2t(S[u][2]);
                Ps[(r0 + 8) * 68 + c + 1] = f2t(S[u][3]);
            }
            __syncwarp();

            // O += P V
            #pragma unroll
            for (int s = 0; s < 8; ++s) {
                unsigned a[4];
                ldsm4(a, Ps + (wid * 16 + lrow) * 68 + s * 8 + lcol);
                #pragma unroll
                for (int u = 0; u < 8; ++u) {
                    unsigned bfr[2];
                    int n = u * 8 + l4;
                    bfr[0] = Vb[(s * 8 + lm) * 72 + n];
                    bfr[1] = Vb[(s * 8 + lm + 4) * 72 + n];
                    mma8(O[u], a, bfr);
                }
            }
        }
        // prefetch next tile's bias into registers
        if (kt + 1 <= ktmax && tid < 192) {
            int dv = q0 - (kt + 1) * 64 + tid - 63;
            breg = (dv >= 0 && dv < Sv) ? g_bias[h * Sv + dv] : 0.0f;
        }
        __syncthreads();
    }

    // epilogue: ctx (tf32) in [b][s][h*64+dk]
    float inv0 = 1.0f / l0v, inv1 = 1.0f / l1v;
    int gr = q0 + r0;
    #pragma unroll
    for (int u = 0; u < 8; ++u) {
        int dk = h * 64 + u * 8 + lm * 2;
        size_t o0 = ((size_t)(b_ * Sv + gr)) * Dv + dk;
        *(uint2*)(g_ctx + o0) = make_uint2(f2t(O[u][0] * inv0), f2t(O[u][1] * inv0));
        size_t o1 = ((size_t)(b_ * Sv + gr + 8)) * Dv + dk;
        *(uint2*)(g_ctx + o1) = make_uint2(f2t(O[u][2] * inv1), f2t(O[u][3] * inv1));
    }
}

// ---------------- launch ----------------
extern "C" void kernel_launch(void* const* d_in, const int* in_sizes, int n_in,
                              void* d_out, int out_size) {
    (void)in_sizes; (void)n_in; (void)out_size;
    const float* hidden   = (const float*)d_in[0];
    const float* rms_w    = (const float*)d_in[2];
    const float* W_qkv    = (const float*)d_in[3];
    const float* W_o      = (const float*)d_in[4];
    const float* rel_bias = (const float*)d_in[5];
    float* out = (float*)d_out;

    unsigned* wqkv_p; cudaGetSymbolAddress((void**)&wqkv_p, g_wqkv);
    unsigned* wo_p;   cudaGetSymbolAddress((void**)&wo_p, g_wo);
    unsigned* nrm_p;  cudaGetSymbolAddress((void**)&nrm_p, g_normed);
    unsigned* ctx_p;  cudaGetSymbolAddress((void**)&ctx_p, g_ctx);

    const int MM_SMEM = (2 * (128 * 36 + 32 * 264)) * 4;                 // 104448
    const int AT_SMEM = (8704 + 8704 + 9216 + 8704) * 4 + 192 * 4 + 64;  // ~142 KB
    cudaFuncSetAttribute(mm_kernel<Nqkv, 0>, cudaFuncAttributeMaxDynamicSharedMemorySize, MM_SMEM);
    cudaFuncSetAttribute(mm_kernel<Dv, 1>,   cudaFuncAttributeMaxDynamicSharedMemorySize, MM_SMEM);
    cudaFuncSetAttribute(attn_kernel,        cudaFuncAttributeMaxDynamicSharedMemorySize, AT_SMEM);

    pre_kernel<<<8192 + 3072 + 1024 + 8, 256>>>(hidden, rms_w, W_qkv, W_o, rel_bias);
    mm_kernel<Nqkv, 0><<<dim3(Nqkv / 256, (Bv * Sv) / 128), 256, MM_SMEM>>>(nrm_p, wqkv_p, nullptr, nullptr);
    attn_kernel<<<dim3(Sv / 128, Bv * Hv), 256, AT_SMEM>>>();
    mm_kernel<Dv, 1><<<dim3(Dv / 256, (Bv * Sv) / 128), 256, MM_SMEM>>>(ctx_p, wo_p, hidden, out);
}

// round 15
// speedup vs baseline: 2.5587x; 1.6074x over previous
#include <cuda_runtime.h>
#include <cuda_fp16.h>
#include <math.h>
#include <stdint.h>

#define Bv 4
#define Sv 2048
#define Dv 1024
#define Hv 16
#define DKv 64
#define Nqkv (3*Hv*DKv)   // 3072

// ---------------- scratch (device globals, fp16) ----------------
__device__ __half g_normed[(size_t)Bv*Sv*Dv];     // [8192][1024]
__device__ __half g_wqkvT[(size_t)Nqkv*Dv];       // W_qkv^T [3072][1024]
__device__ __half g_woT[(size_t)Dv*Dv];           // W_o^T   [1024][1024]
__device__ __half g_q[(size_t)Bv*Hv*Sv*DKv];      // [b][h][s][dk]
__device__ __half g_k[(size_t)Bv*Hv*Sv*DKv];
__device__ __half g_v[(size_t)Bv*Hv*Sv*DKv];
__device__ __half g_ctx[(size_t)Bv*Sv*Dv];        // [b][s][h*64+dk]
__device__ float  g_bias[Hv*Sv];                  // [h][distance]

// ---------------- helpers ----------------
__device__ __forceinline__ unsigned f2h2(float lo, float hi) {
    __half2 h = __floats2half2_rn(lo, hi);
    return *(unsigned*)&h;
}
__device__ __forceinline__ void mma16(float c[4], const unsigned a[4], const unsigned b[2]) {
    asm volatile(
        "mma.sync.aligned.m16n8k16.row.col.f32.f16.f16.f32 "
        "{%0,%1,%2,%3}, {%4,%5,%6,%7}, {%8,%9}, {%0,%1,%2,%3};"
        : "+f"(c[0]), "+f"(c[1]), "+f"(c[2]), "+f"(c[3])
        : "r"(a[0]), "r"(a[1]), "r"(a[2]), "r"(a[3]), "r"(b[0]), "r"(b[1]));
}
__device__ __forceinline__ void ldsm4(unsigned a[4], const __half* p) {
    unsigned addr = (unsigned)__cvta_generic_to_shared(p);
    asm volatile("ldmatrix.sync.aligned.m8n8.x4.shared.b16 {%0,%1,%2,%3}, [%4];"
        : "=r"(a[0]), "=r"(a[1]), "=r"(a[2]), "=r"(a[3]) : "r"(addr));
}
__device__ __forceinline__ void ldsm2(unsigned b[2], const __half* p) {
    unsigned addr = (unsigned)__cvta_generic_to_shared(p);
    asm volatile("ldmatrix.sync.aligned.m8n8.x2.shared.b16 {%0,%1}, [%2];"
        : "=r"(b[0]), "=r"(b[1]) : "r"(addr));
}
__device__ __forceinline__ void ldsm2t(unsigned b[2], const __half* p) {
    unsigned addr = (unsigned)__cvta_generic_to_shared(p);
    asm volatile("ldmatrix.sync.aligned.m8n8.x2.trans.shared.b16 {%0,%1}, [%2];"
        : "=r"(b[0]), "=r"(b[1]) : "r"(addr));
}
__device__ __forceinline__ void cp16(unsigned sdst, const void* gsrc) {
    asm volatile("cp.async.cg.shared.global [%0], [%1], 16;" :: "r"(sdst), "l"(gsrc));
}
#define CP_COMMIT() asm volatile("cp.async.commit_group;")
#define CP_WAIT1()  asm volatile("cp.async.wait_group 1;")
#define CP_WAIT0()  asm volatile("cp.async.wait_group 0;")

// ---------------- fused preprocessing: rmsnorm + 2 weight transpose-converts + bias ----------------
__global__ __launch_bounds__(256) void pre_kernel(const float* __restrict__ x,
                                                  const float* __restrict__ w,
                                                  const float* __restrict__ Wqkv,
                                                  const float* __restrict__ Wo,
                                                  const float* __restrict__ rel_bias) {
    int bx = blockIdx.x;
    int t = threadIdx.x;
    __shared__ float ts[32][33];
    if (bx < 8192) {
        const float* xr = x + (size_t)bx * Dv;
        __half* nr = g_normed + (size_t)bx * Dv;
        float4 v = ((const float4*)xr)[t];
        float ss = v.x*v.x + v.y*v.y + v.z*v.z + v.w*v.w;
        #pragma unroll
        for (int o = 16; o; o >>= 1) ss += __shfl_xor_sync(0xffffffffu, ss, o);
        __shared__ float sred[8];
        if ((t & 31) == 0) sred[t >> 5] = ss;
        __syncthreads();
        if (t < 8) {
            float s2 = sred[t];
            #pragma unroll
            for (int o = 4; o; o >>= 1) s2 += __shfl_xor_sync(0xffu, s2, o);
            if (t == 0) sred[0] = s2;
        }
        __syncthreads();
        float inv = rsqrtf(sred[0] * (1.0f / Dv) + 1e-6f);
        float4 wv = ((const float4*)w)[t];
        uint2 o2;
        o2.x = f2h2(v.x * inv * wv.x, v.y * inv * wv.y);
        o2.y = f2h2(v.z * inv * wv.z, v.w * inv * wv.w);
        *(uint2*)(nr + t * 4) = o2;
    } else if (bx < 8192 + 3072) {
        // W_qkv [1024][3072] -> g_wqkvT [3072][1024] fp16, 32x32 tiles
        int ti = bx - 8192;
        int tn = ti >> 5, tk = ti & 31;
        int k0 = tk * 32, n0 = tn * 32;
        int r = t >> 3, c4 = (t & 7) * 4;
        float4 v = *(const float4*)(Wqkv + (size_t)(k0 + r) * Nqkv + n0 + c4);
        ts[r][c4 + 0] = v.x; ts[r][c4 + 1] = v.y; ts[r][c4 + 2] = v.z; ts[r][c4 + 3] = v.w;
        __syncthreads();
        uint2 o2;
        o2.x = f2h2(ts[c4 + 0][r], ts[c4 + 1][r]);
        o2.y = f2h2(ts[c4 + 2][r], ts[c4 + 3][r]);
        *(uint2*)(g_wqkvT + (size_t)(n0 + r) * Dv + k0 + c4) = o2;
    } else if (bx < 8192 + 3072 + 1024) {
        int ti = bx - 8192 - 3072;
        int tn = ti >> 5, tk = ti & 31;
        int k0 = tk * 32, n0 = tn * 32;
        int r = t >> 3, c4 = (t & 7) * 4;
        float4 v = *(const float4*)(Wo + (size_t)(k0 + r) * Dv + n0 + c4);
        ts[r][c4 + 0] = v.x; ts[r][c4 + 1] = v.y; ts[r][c4 + 2] = v.z; ts[r][c4 + 3] = v.w;
        __syncthreads();
        uint2 o2;
        o2.x = f2h2(ts[c4 + 0][r], ts[c4 + 1][r]);
        o2.y = f2h2(ts[c4 + 2][r], ts[c4 + 3][r]);
        *(uint2*)(g_woT + (size_t)(n0 + r) * Dv + k0 + c4) = o2;
    } else {
        int d = (bx - 12288) * 256 + t;
        int bucket;
        if (d < 16) bucket = d;
        else {
            float v = (logf((float)d / 16.0f) / 2.0794415416798357f) * 16.0f;
            bucket = 16 + (int)v;
            if (bucket > 31) bucket = 31;
        }
        #pragma unroll
        for (int h = 0; h < Hv; ++h)
            g_bias[h * Sv + d] = rel_bias[bucket * Hv + h];
    }
}

// ---------------- fp16 HMMA GEMM: C[8192,NN] = A[8192,1024] @ Bt[NN,1024]^T ----------------
// block 128x256, 8 warps (2x4), warp tile 64x64, K-tile 32 (2 k16 steps), cp.async double buffer.
// MODE 0: scatter qkv (fp16 out). MODE 1: out = acc + hidden (fp32 out).
template<int NN, int MODE>
__global__ __launch_bounds__(256, 1) void mm_kernel(const __half* __restrict__ A,
                                                    const __half* __restrict__ Bt,
                                                    const float* __restrict__ hidden,
                                                    float* __restrict__ outp) {
    const int LDA = 40, LDB = 40;       // halfs; 80B stride -> conflict-free ldmatrix
    const int ABUF = 128 * LDA;         // 5120 halfs
    const int BBUF = 256 * LDB;         // 10240 halfs
    extern __shared__ __half sh[];
    __half* As = sh;                    // 2 x ABUF
    __half* Bs = sh + 2 * ABUF;         // 2 x BBUF

    int m0 = blockIdx.y * 128, n0 = blockIdx.x * 256;
    int tid = threadIdx.x;
    int wid = tid >> 5, l = tid & 31;
    int wm = wid >> 2, wn = wid & 3;     // 2 x 4 warps
    int l4 = l >> 2, lm = l & 3;
    int lrow = l & 15;
    int hcol = (l >> 4) * 8;             // halfs

    unsigned sAbase = (unsigned)__cvta_generic_to_shared(As);
    unsigned sBbase = (unsigned)__cvta_generic_to_shared(Bs);

    auto issue = [&](int kt, int buf) {
        #pragma unroll
        for (int i = 0; i < 2; ++i) {               // A: 128 rows x 4 x 16B
            int idx = tid + i * 256;
            int row = idx >> 2, q = idx & 3;
            cp16(sAbase + buf * (ABUF * 2) + row * 80 + q * 16,
                 A + (size_t)(m0 + row) * Dv + kt * 32 + q * 8);
        }
        #pragma unroll
        for (int i = 0; i < 4; ++i) {               // B: 256 rows x 4 x 16B
            int idx = tid + i * 256;
            int row = idx >> 2, q = idx & 3;
            cp16(sBbase + buf * (BBUF * 2) + row * 80 + q * 16,
                 Bt + (size_t)(n0 + row) * Dv + kt * 32 + q * 8);
        }
    };

    float acc[4][8][4];
    #pragma unroll
    for (int t = 0; t < 4; t++)
        #pragma unroll
        for (int u = 0; u < 8; u++)
            #pragma unroll
            for (int e = 0; e < 4; e++) acc[t][u][e] = 0.0f;

    issue(0, 0); CP_COMMIT();
    issue(1, 1); CP_COMMIT();

    const int NT = Dv / 32;   // 32 K-tiles
    for (int kt = 0; kt < NT; ++kt) {
        if (kt + 1 < NT) CP_WAIT1(); else CP_WAIT0();
        __syncthreads();
        const __half* Ab = As + (kt & 1) * ABUF;
        const __half* Bb = Bs + (kt & 1) * BBUF;
        #pragma unroll
        for (int s = 0; s < 2; ++s) {
            unsigned a[4][4], b[8][2];
            #pragma unroll
            for (int t = 0; t < 4; ++t)
                ldsm4(a[t], Ab + (wm * 64 + t * 16 + lrow) * LDA + s * 16 + hcol);
            #pragma unroll
            for (int u = 0; u < 8; ++u)
                ldsm2(b[u], Bb + (wn * 64 + u * 8 + (l & 7)) * LDB + s * 16 + ((l >> 3) & 1) * 8);
            #pragma unroll
            for (int t = 0; t < 4; ++t)
                #pragma unroll
                for (int u = 0; u < 8; ++u)
                    mma16(acc[t][u], a[t], b[u]);
        }
        __syncthreads();
        if (kt + 2 < NT) issue(kt + 2, kt & 1);
        CP_COMMIT();
    }

    // epilogue
    if (MODE == 0) {
        #pragma unroll
        for (int t = 0; t < 4; ++t) {
            int r = m0 + wm * 64 + t * 16 + l4;
            int b0r = r >> 11, s0r = r & 2047;
            #pragma unroll
            for (int u = 0; u < 8; ++u) {
                int cb = n0 + wn * 64 + u * 8 + lm * 2;
                int three = cb >> 10;
                int rem = cb & 1023;
                int h = rem >> 6, dk = rem & 63;
                __half* dst = (three == 0) ? g_q : ((three == 1) ? g_k : g_v);
                size_t off0 = ((((size_t)b0r * Hv + h) * Sv + s0r) * DKv + dk);
                *(unsigned*)(dst + off0) = f2h2(acc[t][u][0], acc[t][u][1]);
                size_t off1 = ((((size_t)b0r * Hv + h) * Sv + (s0r + 8)) * DKv + dk);
                *(unsigned*)(dst + off1) = f2h2(acc[t][u][2], acc[t][u][3]);
            }
        }
    } else {
        #pragma unroll
        for (int t = 0; t < 4; ++t) {
            int r = m0 + wm * 64 + t * 16 + l4;
            #pragma unroll
            for (int u = 0; u < 8; ++u) {
                int cb = n0 + wn * 64 + u * 8 + lm * 2;
                float2 h0 = *(const float2*)(hidden + (size_t)r * Dv + cb);
                *(float2*)(outp + (size_t)r * Dv + cb) =
                    make_float2(acc[t][u][0] + h0.x, acc[t][u][1] + h0.y);
                float2 h1 = *(const float2*)(hidden + (size_t)(r + 8) * Dv + cb);
                *(float2*)(outp + (size_t)(r + 8) * Dv + cb) =
                    make_float2(acc[t][u][2] + h1.x, acc[t][u][3] + h1.y);
            }
        }
    }
}

// ---------------- Flash attention on fp16 HMMA ----------------
// q-tile 128 (8 warps x 16 rows), k-tile 64, cp.async double-buffered K/V.
__global__ __launch_bounds__(256) void attn_kernel() {
    int qt = (int)(gridDim.x - 1) - (int)blockIdx.x;  // longest blocks first
    int bh = blockIdx.y;
    int b_ = bh >> 4, h = bh & 15;
    int q0 = qt * 128;

    const int LDQ = 72, LDK = 72, LDV = 72, LDP = 72;   // halfs; 144B stride
    // halfs offsets: Q[128*72]=9216, K 2x[64*72]=4608, V 2x4608, P 9216, bias floats
    extern __shared__ __half sm[];
    __half* Qs = sm;                         // 9216
    __half* Ks = sm + 9216;                  // 2 x 4608
    __half* Vs = sm + 9216 + 9216;           // 2 x 4608
    __half* Ps = sm + 9216 + 9216 + 9216;    // 9216
    float* bs = (float*)(sm + 36864);        // 192 floats

    const __half* Qg = g_q + (size_t)bh * Sv * DKv;
    const __half* Kg = g_k + (size_t)bh * Sv * DKv;
    const __half* Vg = g_v + (size_t)bh * Sv * DKv;

    int tid = threadIdx.x, wid = tid >> 5, l = tid & 31;
    int l4 = l >> 2, lm = l & 3;
    int r0 = wid * 16 + l4;
    int lrow = l & 15;
    int hcol = (l >> 4) * 8;

    unsigned sKbase = (unsigned)__cvta_generic_to_shared(Ks);
    unsigned sVbase = (unsigned)__cvta_generic_to_shared(Vs);

    auto issueKV = [&](int kt, int buf) {
        int k0 = kt * 64;
        #pragma unroll
        for (int i = 0; i < 2; ++i) {
            int idx = tid + i * 256;
            int row = idx >> 3, q = idx & 7;
            cp16(sKbase + buf * 9216 + row * 144 + q * 16,
                 Kg + (size_t)(k0 + row) * DKv + q * 8);
            cp16(sVbase + buf * 9216 + row * 144 + q * 16,
                 Vg + (size_t)(k0 + row) * DKv + q * 8);
        }
    };

    // stage Q (128 rows x 64 halfs)
    #pragma unroll
    for (int i = 0; i < 4; ++i) {
        int idx = tid + i * 256;
        int row = idx >> 3, q = idx & 7;
        *(uint4*)&Qs[row * LDQ + q * 8] = *(const uint4*)(Qg + (size_t)(q0 + row) * DKv + q * 8);
    }

    int ktmax = 2 * qt + 1;
    issueKV(0, 0); CP_COMMIT();

    float breg = 0.0f;
    if (tid < 192) {
        int dv = q0 + tid - 63;
        breg = (dv >= 0 && dv < Sv) ? g_bias[h * Sv + dv] : 0.0f;
    }

    float m0v = -1e30f, m1v = -1e30f, l0v = 0.0f, l1v = 0.0f;
    float O[8][4];
    #pragma unroll
    for (int u = 0; u < 8; ++u)
        #pragma unroll
        for (int e = 0; e < 4; ++e) O[u][e] = 0.0f;

    for (int kt = 0; kt <= ktmax; ++kt) {
        int k0 = kt * 64;
        int buf = kt & 1;
        if (kt + 1 <= ktmax) issueKV(kt + 1, buf ^ 1);
        CP_COMMIT();
        if (tid < 192) bs[tid] = breg;
        if (kt == ktmax) CP_WAIT0(); else CP_WAIT1();
        __syncthreads();

        const __half* Kb = Ks + buf * 4608;
        const __half* Vb = Vs + buf * 4608;

        bool active = (k0 <= q0 + wid * 16 + 15);   // warp-uniform
        if (active) {
            // S = Q K^T  (4 k16 steps over dk=64)
            float S[8][4];
            #pragma unroll
            for (int u = 0; u < 8; ++u)
                #pragma unroll
                for (int e = 0; e < 4; ++e) S[u][e] = 0.0f;
            #pragma unroll
            for (int s = 0; s < 4; ++s) {
                unsigned a[4];
                ldsm4(a, Qs + (wid * 16 + lrow) * LDQ + s * 16 + hcol);
                #pragma unroll
                for (int u = 0; u < 8; ++u) {
                    unsigned bfr[2];
                    ldsm2(bfr, Kb + (u * 8 + (l & 7)) * LDK + s * 16 + ((l >> 3) & 1) * 8);
                    mma16(S[u], a, bfr);
                }
            }

            // bias + causal, row maxima
            int dq = q0 - k0;
            float mx0 = -1e30f, mx1 = -1e30f;
            #pragma unroll
            for (int u = 0; u < 8; ++u) {
                int c = u * 8 + lm * 2;
                #pragma unroll
                for (int e = 0; e < 2; ++e) {
                    int cc = c + e;
                    int d0 = dq + r0 - cc;
                    S[u][e]     = (d0 >= 0) ? S[u][e] + bs[r0 - cc + 63] : -1e30f;
                    int d1 = dq + r0 + 8 - cc;
                    S[u][2 + e] = (d1 >= 0) ? S[u][2 + e] + bs[r0 + 8 - cc + 63] : -1e30f;
                    mx0 = fmaxf(mx0, S[u][e]);
                    mx1 = fmaxf(mx1, S[u][2 + e]);
                }
            }
            mx0 = fmaxf(mx0, __shfl_xor_sync(0xffffffffu, mx0, 1));
            mx0 = fmaxf(mx0, __shfl_xor_sync(0xffffffffu, mx0, 2));
            mx1 = fmaxf(mx1, __shfl_xor_sync(0xffffffffu, mx1, 1));
            mx1 = fmaxf(mx1, __shfl_xor_sync(0xffffffffu, mx1, 2));

            float mn0 = fmaxf(m0v, mx0), mn1 = fmaxf(m1v, mx1);
            float sc0 = __expf(m0v - mn0), sc1 = __expf(m1v - mn1);
            m0v = mn0; m1v = mn1;
            float rs0 = 0.0f, rs1 = 0.0f;
            #pragma unroll
            for (int u = 0; u < 8; ++u) {
                #pragma unroll
                for (int e = 0; e < 2; ++e) {
                    float p0 = __expf(S[u][e] - mn0);     S[u][e] = p0;     rs0 += p0;
                    float p1 = __expf(S[u][2 + e] - mn1); S[u][2 + e] = p1; rs1 += p1;
                }
            }
            rs0 += __shfl_xor_sync(0xffffffffu, rs0, 1);
            rs0 += __shfl_xor_sync(0xffffffffu, rs0, 2);
            rs1 += __shfl_xor_sync(0xffffffffu, rs1, 1);
            rs1 += __shfl_xor_sync(0xffffffffu, rs1, 2);
            l0v = l0v * sc0 + rs0;
            l1v = l1v * sc1 + rs1;
            #pragma unroll
            for (int u = 0; u < 8; ++u) {
                O[u][0] *= sc0; O[u][1] *= sc0;
                O[u][2] *= sc1; O[u][3] *= sc1;
            }
            // P -> fp16 smem (packed half2 stores)
            #pragma unroll
            for (int u = 0; u < 8; ++u) {
                int c = u * 8 + lm * 2;
                *(unsigned*)&Ps[r0 * LDP + c]       = f2h2(S[u][0], S[u][1]);
                *(unsigned*)&Ps[(r0 + 8) * LDP + c] = f2h2(S[u][2], S[u][3]);
            }
            __syncwarp();

            // O += P V  (4 k16 steps over keys; V via ldmatrix.trans)
            #pragma unroll
            for (int s = 0; s < 4; ++s) {
                unsigned a[4];
                ldsm4(a, Ps + (wid * 16 + lrow) * LDP + s * 16 + hcol);
                #pragma unroll
                for (int u = 0; u < 8; ++u) {
                    unsigned bfr[2];
                    ldsm2t(bfr, Vb + (s * 16 + (l & 15)) * LDV + u * 8);
                    mma16(O[u], a, bfr);
                }
            }
        }
        // prefetch next tile's bias into registers
        if (kt + 1 <= ktmax && tid < 192) {
            int dv = q0 - (kt + 1) * 64 + tid - 63;
            breg = (dv >= 0 && dv < Sv) ? g_bias[h * Sv + dv] : 0.0f;
        }
        __syncthreads();
    }

    // epilogue: ctx (fp16) in [b][s][h*64+dk]
    float inv0 = 1.0f / l0v, inv1 = 1.0f / l1v;
    int gr = q0 + r0;
    #pragma unroll
    for (int u = 0; u < 8; ++u) {
        int dk = h * 64 + u * 8 + lm * 2;
        size_t o0 = ((size_t)(b_ * Sv + gr)) * Dv + dk;
        *(unsigned*)(g_ctx + o0) = f2h2(O[u][0] * inv0, O[u][1] * inv0);
        size_t o1 = ((size_t)(b_ * Sv + gr + 8)) * Dv + dk;
        *(unsigned*)(g_ctx + o1) = f2h2(O[u][2] * inv1, O[u][3] * inv1);
    }
}

// ---------------- launch ----------------
extern "C" void kernel_launch(void* const* d_in, const int* in_sizes, int n_in,
                              void* d_out, int out_size) {
    (void)in_sizes; (void)n_in; (void)out_size;
    const float* hidden   = (const float*)d_in[0];
    const float* rms_w    = (const float*)d_in[2];
    const float* W_qkv    = (const float*)d_in[3];
    const float* W_o      = (const float*)d_in[4];
    const float* rel_bias = (const float*)d_in[5];
    float* out = (float*)d_out;

    __half* wqkvT_p; cudaGetSymbolAddress((void**)&wqkvT_p, g_wqkvT);
    __half* woT_p;   cudaGetSymbolAddress((void**)&woT_p, g_woT);
    __half* nrm_p;   cudaGetSymbolAddress((void**)&nrm_p, g_normed);
    __half* ctx_p;   cudaGetSymbolAddress((void**)&ctx_p, g_ctx);

    const int MM_SMEM = (2 * (128 * 40 + 256 * 40)) * 2;   // 61440 B
    const int AT_SMEM = 36864 * 2 + 192 * 4 + 64;          // ~74.6 KB
    cudaFuncSetAttribute(mm_kernel<Nqkv, 0>, cudaFuncAttributeMaxDynamicSharedMemorySize, MM_SMEM);
    cudaFuncSetAttribute(mm_kernel<Dv, 1>,   cudaFuncAttributeMaxDynamicSharedMemorySize, MM_SMEM);
    cudaFuncSetAttribute(attn_kernel,        cudaFuncAttributeMaxDynamicSharedMemorySize, AT_SMEM);

    pre_kernel<<<8192 + 3072 + 1024 + 8, 256>>>(hidden, rms_w, W_qkv, W_o, rel_bias);
    mm_kernel<Nqkv, 0><<<dim3(Nqkv / 256, (Bv * Sv) / 128), 256, MM_SMEM>>>(nrm_p, wqkvT_p, nullptr, nullptr);
    attn_kernel<<<dim3(Sv / 128, Bv * Hv), 256, AT_SMEM>>>();
    mm_kernel<Dv, 1><<<dim3(Dv / 256, (Bv * Sv) / 128), 256, MM_SMEM>>>(ctx_p, woT_p, hidden, out);
}